// round 14
// baseline (speedup 1.0000x reference)
#include <cuda_runtime.h>
#include <cuda_bf16.h>
#include <stdint.h>

#define NN 256            // N (atoms per batch)
#define MAXB 512          // max batch
#define GR 16             // output rows per gather block
#define TK 16             // tile rows for colsum staging
#define NT (NN / TK)      // 16 tiles

__device__ int       g_perm[MAXB * NN];
__device__ float     g_ss2[MAXB * NN], g_v42[MAXB * NN];
__device__ long long g_vi2[MAXB * NN];

// ---------------------------------------------------------------------------
// colsum_pass: block streams one 256KB matrix through a 2-deep cp.async ring
// (identical tile structure to R13). Voter arithmetic per column BIT-IDENTICAL
// to passing R7-R13: seq chain, IC4 round-robin left-chain, int64 fixed-point.
// do_sort=0 (D2 pass, runs FIRST): store sums to global side-2 arrays.
// do_sort=1 (D1 pass, runs LAST so D1 stays L2-resident for gather): fused
// bitonic majority-vote lexsort using local side-1 sums + global side-2 sums;
// writes g_perm and the gathered-types output tail.
// ---------------------------------------------------------------------------
__global__ __launch_bounds__(256) void colsum_pass(
    const float* __restrict__ M, int do_sort,
    const int* __restrict__ t1, const int* __restrict__ t2,
    float* __restrict__ out, long long base, long long out_size)
{
    const int b   = blockIdx.x;
    const int tid = threadIdx.x;
    const float4* q = (const float4*)(M + (size_t)b * NN * NN);

    __shared__ float tile[2][TK * NN];   // 2 x 16KB

    #define LOAD_TILE(buf, t0)                                                 \
        {                                                                      \
            uint32_t _base = (uint32_t)__cvta_generic_to_shared(&tile[buf][0]);\
            _Pragma("unroll")                                                  \
            for (int m = 0; m < 4; ++m) {                                      \
                int idx = m * 256 + tid;                                       \
                asm volatile("cp.async.cg.shared.global [%0], [%1], 16;\n"     \
                             :: "r"(_base + idx * 16),                         \
                                "l"(q + (size_t)(t0) * 64 + idx)               \
                             : "memory");                                      \
            }                                                                  \
            asm volatile("cp.async.commit_group;\n" ::: "memory");             \
        }

    float ss = 0.f, a0 = 0.f, a1 = 0.f, a2 = 0.f, a3 = 0.f;
    long long acc = 0;
    const float SCALE = 1099511627776.0f;   // 2^40 (exact power-of-two scale)

    LOAD_TILE(0, 0);

#pragma unroll 1
    for (int ti = 0; ti < NT; ++ti) {
        if (ti + 1 < NT) {
            LOAD_TILE((ti + 1) & 1, (ti + 1) * TK);
            asm volatile("cp.async.wait_group 1;\n" ::: "memory");
        } else {
            asm volatile("cp.async.wait_group 0;\n" ::: "memory");
        }
        __syncthreads();

        const float* T = &tile[ti & 1][0];
        float x[TK];
#pragma unroll
        for (int r = 0; r < TK; ++r) x[r] = T[r * NN + tid];   // conflict-free

        // strict sequential chain (identical order to R7-R13)
#pragma unroll
        for (int r = 0; r < TK; ++r) ss = __fadd_rn(ss, x[r]);
        // IC4 round-robin: k = ti*16 + r, k%4 == r%4 (TK multiple of 4)
#pragma unroll
        for (int r = 0; r < TK; r += 4) {
            a0 = __fadd_rn(a0, x[r + 0]);
            a1 = __fadd_rn(a1, x[r + 1]);
            a2 = __fadd_rn(a2, x[r + 2]);
            a3 = __fadd_rn(a3, x[r + 3]);
        }
        // exact fixed-point truth (order-free)
#pragma unroll
        for (int r = 0; r < TK; ++r) acc += __float2ll_rn(x[r] * SCALE);

        __syncthreads();
    }
    #undef LOAD_TILE

    const float v4 = __fadd_rn(__fadd_rn(__fadd_rn(a0, a1), a2), a3);

    if (!do_sort) {
        g_ss2[b * NN + tid] = ss;
        g_v42[b * NN + tid] = v4;
        g_vi2[b * NN + tid] = acc;
        return;
    }

    // ---------- fused sort (D1 pass): side-1 sums live in registers ----------
    __shared__ float     vs1[NN], v41[NN];
    __shared__ long long vi1[NN];
    __shared__ float     vs2[NN], v42[NN];
    __shared__ long long vi2[NN];
    __shared__ int       ty1s[NN], ty2s[NN];
    __shared__ int       idx1[NN], idx2[NN];

    vs1[tid] = ss;
    v41[tid] = v4;
    vi1[tid] = acc;
    vs2[tid] = g_ss2[b * NN + tid];
    v42[tid] = g_v42[b * NN + tid];
    vi2[tid] = g_vi2[b * NN + tid];
    ty1s[tid] = t1[b * NN + tid];
    ty2s[tid] = t2[b * NN + tid];
    idx1[tid] = tid;
    idx2[tid] = tid;
    __syncthreads();

    #define BEFORE(ty, vsq, v4a, vib, i, j, res)                              \
        {                                                                     \
            int _ti = ty[i], _tj = ty[j];                                     \
            if (_ti != _tj) { res = (_ti < _tj); }                            \
            else {                                                            \
                int _v = 0;                                                   \
                _v += (vsq[i] < vsq[j]) || (vsq[i] == vsq[j] && (i) < (j));   \
                _v += (v4a[i] < v4a[j]) || (v4a[i] == v4a[j] && (i) < (j));   \
                _v += (vib[i] < vib[j]) || (vib[i] == vib[j] && (i) < (j));   \
                res = (_v >= 2);                                              \
            }                                                                 \
        }

    for (int k = 2; k <= NN; k <<= 1) {
        for (int j = k >> 1; j > 0; j >>= 1) {
            int partner = tid ^ j;
            if (partner > tid) {
                bool up = ((tid & k) == 0);
                {
                    int ia = idx1[tid], ib = idx1[partner];
                    bool a_before_b;
                    BEFORE(ty1s, vs1, v41, vi1, ia, ib, a_before_b);
                    if (up == !a_before_b) { idx1[tid] = ib; idx1[partner] = ia; }
                }
                {
                    int ia = idx2[tid], ib = idx2[partner];
                    bool a_before_b;
                    BEFORE(ty2s, vs2, v42, vi2, ia, ib, a_before_b);
                    if (up == !a_before_b) { idx2[tid] = ib; idx2[partner] = ia; }
                }
            }
            __syncthreads();
        }
    }
    #undef BEFORE

    // perm[order2[t]] = order1[t]
    g_perm[b * NN + idx2[tid]] = idx1[tid];

    // gathered-types tail: out[base + b*NN + pos] = types1[source atom]
    long long o = base + (long long)b * NN + idx2[tid];
    if (o < out_size) out[o] = (float)ty1s[idx1[tid]];
}

// ---------------------------------------------------------------------------
// Gather: out[b,i,j] = D1[b, perm[i], perm[j]]. GR rows per block; float4
// loads AND float4 stores. D1 should be ~fully L2-resident (D1 pass ran last).
// ---------------------------------------------------------------------------
__global__ void gather_kernel(const float* __restrict__ D1,
                              float* __restrict__ out) {
    const int b   = blockIdx.y;
    const int i0  = blockIdx.x * GR;
    const int tid = threadIdx.x;   // 256 threads

    __shared__ int   sp[NN];
    __shared__ float sd[GR][NN];

    sp[tid] = g_perm[b * NN + tid];
    __syncthreads();

    const float4* src4 = (const float4*)(D1 + (size_t)b * NN * NN);
#pragma unroll
    for (int m = 0; m < GR * 64 / 256; ++m) {
        int q  = m * 256 + tid;     // over GR*64 float4 slots
        int r  = q >> 6;            // row
        int c4 = q & 63;
        int s  = sp[i0 + r];
        ((float4*)sd[r])[c4] = src4[(size_t)s * 64 + c4];
    }
    __syncthreads();

    float4* ob = (float4*)(out + ((size_t)b * NN + i0) * NN);
#pragma unroll
    for (int m = 0; m < GR * 64 / 256; ++m) {
        int q  = m * 256 + tid;
        int r  = q >> 6;
        int c4 = q & 63;
        float4 v;
        v.x = sd[r][sp[c4 * 4 + 0]];
        v.y = sd[r][sp[c4 * 4 + 1]];
        v.z = sd[r][sp[c4 * 4 + 2]];
        v.w = sd[r][sp[c4 * 4 + 3]];
        ob[(size_t)r * 64 + c4] = v;
    }
}

extern "C" void kernel_launch(void* const* d_in, const int* in_sizes, int n_in,
                              void* d_out, int out_size) {
    const float* D1 = (const float*)d_in[0];
    const float* D2 = (const float*)d_in[1];
    const int*   t1 = (const int*)d_in[2];
    const int*   t2 = (const int*)d_in[3];
    float* out = (float*)d_out;

    int B = in_sizes[0] / (NN * NN);
    if (B > MAXB) B = MAXB;

    long long base = (long long)B * NN * NN;

    // Pass 1: D2 (evicted later, doesn't matter). Pass 2: D1 LAST so it is
    // L2-resident (128MB vs 126MB L2) when gather re-reads it; fused sort.
    colsum_pass<<<B, 256>>>(D2, 0, t1, t2, out, base, (long long)out_size);
    colsum_pass<<<B, 256>>>(D1, 1, t1, t2, out, base, (long long)out_size);

    dim3 ggrid(NN / GR, B);
    gather_kernel<<<ggrid, 256>>>(D1, out);
}

// round 15
// speedup vs baseline: 1.0297x; 1.0297x over previous
#include <cuda_runtime.h>
#include <cuda_bf16.h>
#include <stdint.h>

#define NN 256            // N (atoms per batch)
#define TK 16             // tile rows for streaming
#define NT (NN / TK)      // 16 tiles

// ---------------------------------------------------------------------------
// Fully fused per-batch kernel: colsum(D2) -> colsum(D1) -> bitonic majority
// sort -> types tail -> symmetric gather, all in one block. D1[b] is re-read
// by the gather phase immediately after its colsum pass -> L2-resident.
// Voter arithmetic per column BIT-IDENTICAL to passing R7-R14:
//   seq  : strict sequential chain over k
//   IC4  : a[k%4] accumulators in increasing k, left-chain combine
//   truth: exact fixed-point int64 (order-free)
// ---------------------------------------------------------------------------

__device__ __forceinline__ void colsum_stream(const float4* __restrict__ q,
                                              int tid,
                                              float (*tile)[TK * NN],
                                              float& ss_o, float& v4_o,
                                              long long& acc_o) {
    #define LOAD_TILE(buf, t0)                                                 \
        {                                                                      \
            uint32_t _base = (uint32_t)__cvta_generic_to_shared(&tile[buf][0]);\
            _Pragma("unroll")                                                  \
            for (int m = 0; m < 4; ++m) {                                      \
                int idx = m * 256 + tid;                                       \
                asm volatile("cp.async.cg.shared.global [%0], [%1], 16;\n"     \
                             :: "r"(_base + idx * 16),                         \
                                "l"(q + (size_t)(t0) * 64 + idx)               \
                             : "memory");                                      \
            }                                                                  \
            asm volatile("cp.async.commit_group;\n" ::: "memory");             \
        }

    float ss = 0.f, a0 = 0.f, a1 = 0.f, a2 = 0.f, a3 = 0.f;
    long long acc = 0;
    const float SCALE = 1099511627776.0f;   // 2^40 (exact power-of-two scale)

    LOAD_TILE(0, 0);

#pragma unroll 1
    for (int ti = 0; ti < NT; ++ti) {
        if (ti + 1 < NT) {
            LOAD_TILE((ti + 1) & 1, (ti + 1) * TK);
            asm volatile("cp.async.wait_group 1;\n" ::: "memory");
        } else {
            asm volatile("cp.async.wait_group 0;\n" ::: "memory");
        }
        __syncthreads();

        const float* T = &tile[ti & 1][0];
        float x[TK];
#pragma unroll
        for (int r = 0; r < TK; ++r) x[r] = T[r * NN + tid];   // conflict-free

        // strict sequential chain (identical order to R7-R14)
#pragma unroll
        for (int r = 0; r < TK; ++r) ss = __fadd_rn(ss, x[r]);
        // IC4 round-robin: k = ti*16 + r, k%4 == r%4 (TK multiple of 4)
#pragma unroll
        for (int r = 0; r < TK; r += 4) {
            a0 = __fadd_rn(a0, x[r + 0]);
            a1 = __fadd_rn(a1, x[r + 1]);
            a2 = __fadd_rn(a2, x[r + 2]);
            a3 = __fadd_rn(a3, x[r + 3]);
        }
        // exact fixed-point truth (order-free)
#pragma unroll
        for (int r = 0; r < TK; ++r) acc += __float2ll_rn(x[r] * SCALE);

        __syncthreads();
    }
    #undef LOAD_TILE

    ss_o  = ss;
    v4_o  = __fadd_rn(__fadd_rn(__fadd_rn(a0, a1), a2), a3);
    acc_o = acc;
}

__global__ __launch_bounds__(256) void fused_kernel(
    const float* __restrict__ D1, const float* __restrict__ D2,
    const int* __restrict__ t1, const int* __restrict__ t2,
    float* __restrict__ out, long long base, long long out_size)
{
    const int b   = blockIdx.x;
    const int tid = threadIdx.x;

    __shared__ float     tile[2][TK * NN];                 // 32 KB ring
    __shared__ float     vs1[NN], v41[NN], vs2[NN], v42[NN];
    __shared__ long long vi1[NN], vi2[NN];
    __shared__ int       ty1s[NN], ty2s[NN], idx1[NN], idx2[NN], sp[NN];

    // ---- phase A: colsum D2[b] (first, so D1 is freshest in L2) ----
    {
        float ss, v4; long long acc;
        colsum_stream((const float4*)(D2 + (size_t)b * NN * NN), tid, tile,
                      ss, v4, acc);
        vs2[tid] = ss; v42[tid] = v4; vi2[tid] = acc;
    }

    // ---- phase B: colsum D1[b] ----
    float ss1r, v41r; long long vi1r;
    colsum_stream((const float4*)(D1 + (size_t)b * NN * NN), tid, tile,
                  ss1r, v41r, vi1r);
    vs1[tid] = ss1r; v41[tid] = v41r; vi1[tid] = vi1r;

    ty1s[tid] = t1[b * NN + tid];
    ty2s[tid] = t2[b * NN + tid];
    idx1[tid] = tid;
    idx2[tid] = tid;
    __syncthreads();

    // ---- phase C: bitonic majority-vote lexsort (identical to R7-R14) ----
    #define BEFORE(ty, vsq, v4a, vib, i, j, res)                              \
        {                                                                     \
            int _ti = ty[i], _tj = ty[j];                                     \
            if (_ti != _tj) { res = (_ti < _tj); }                            \
            else {                                                            \
                int _v = 0;                                                   \
                _v += (vsq[i] < vsq[j]) || (vsq[i] == vsq[j] && (i) < (j));   \
                _v += (v4a[i] < v4a[j]) || (v4a[i] == v4a[j] && (i) < (j));   \
                _v += (vib[i] < vib[j]) || (vib[i] == vib[j] && (i) < (j));   \
                res = (_v >= 2);                                              \
            }                                                                 \
        }

    for (int k = 2; k <= NN; k <<= 1) {
        for (int j = k >> 1; j > 0; j >>= 1) {
            int partner = tid ^ j;
            if (partner > tid) {
                bool up = ((tid & k) == 0);
                {
                    int ia = idx1[tid], ib = idx1[partner];
                    bool a_before_b;
                    BEFORE(ty1s, vs1, v41, vi1, ia, ib, a_before_b);
                    if (up == !a_before_b) { idx1[tid] = ib; idx1[partner] = ia; }
                }
                {
                    int ia = idx2[tid], ib = idx2[partner];
                    bool a_before_b;
                    BEFORE(ty2s, vs2, v42, vi2, ia, ib, a_before_b);
                    if (up == !a_before_b) { idx2[tid] = ib; idx2[partner] = ia; }
                }
            }
            __syncthreads();
        }
    }
    #undef BEFORE

    // perm[order2[t]] = order1[t]
    sp[idx2[tid]] = idx1[tid];

    // types tail: out[base + b*NN + pos] = types1[source atom]
    {
        long long o = base + (long long)b * NN + idx2[tid];
        if (o < out_size) out[o] = (float)ty1s[idx1[tid]];
    }
    __syncthreads();

    // ---- phase D: gather out[b,i,j] = D1[b, sp[i], sp[j]] (D1[b] in L2) ----
    const float4* src4 = (const float4*)(D1 + (size_t)b * NN * NN);
    float4*       ob   = (float4*)(out + (size_t)b * NN * NN);

#pragma unroll 1
    for (int g = 0; g < NN / TK; ++g) {
        const int i0  = g * TK;
        float* T = &tile[g & 1][0];

        // stage TK source rows (contiguous float4 loads, L2 hits)
#pragma unroll
        for (int m = 0; m < 4; ++m) {
            int q  = m * 256 + tid;     // TK*64 = 1024 slots
            int r  = q >> 6;
            int c4 = q & 63;
            int s  = sp[i0 + r];
            ((float4*)T)[r * 64 + c4] = src4[(size_t)s * 64 + c4];
        }
        __syncthreads();

        // permuted-column writes (float4 stores)
#pragma unroll
        for (int m = 0; m < 4; ++m) {
            int q  = m * 256 + tid;
            int r  = q >> 6;
            int c4 = q & 63;
            float4 v;
            v.x = T[r * NN + sp[c4 * 4 + 0]];
            v.y = T[r * NN + sp[c4 * 4 + 1]];
            v.z = T[r * NN + sp[c4 * 4 + 2]];
            v.w = T[r * NN + sp[c4 * 4 + 3]];
            ob[(size_t)(i0 + r) * 64 + c4] = v;
        }
        // write(g) [buf g&1] vs stage(g+2) [same buf]: every thread passes
        // through stage(g+1)'s implicit ordering + the sync below first.
        __syncthreads();
    }
}

extern "C" void kernel_launch(void* const* d_in, const int* in_sizes, int n_in,
                              void* d_out, int out_size) {
    const float* D1 = (const float*)d_in[0];
    const float* D2 = (const float*)d_in[1];
    const int*   t1 = (const int*)d_in[2];
    const int*   t2 = (const int*)d_in[3];
    float* out = (float*)d_out;

    int B = in_sizes[0] / (NN * NN);
    long long base = (long long)B * NN * NN;

    fused_kernel<<<B, 256>>>(D1, D2, t1, t2, out, base, (long long)out_size);
}

// round 16
// speedup vs baseline: 1.0992x; 1.0674x over previous
#include <cuda_runtime.h>
#include <cuda_bf16.h>
#include <stdint.h>

#define NN 256            // N (atoms per batch)
#define MAXB 512          // max batch
#define GR 16             // output rows per gather block
#define TK 16             // tile rows for colsum staging
#define NT (NN / TK)      // 16 tiles

__device__ int       g_perm[MAXB * NN];
__device__ float     g_ss1[MAXB * NN], g_v41[MAXB * NN];
__device__ long long g_vi1[MAXB * NN];
__device__ float     g_ss2[MAXB * NN], g_v42[MAXB * NN];
__device__ long long g_vi2[MAXB * NN];

// ---------------------------------------------------------------------------
// Reduction (R13 structure): block streams its 256KB matrix contiguously
// through a 2-deep cp.async ring. NEW: D2 blocks load with an L2 evict_first
// cache policy so D2 never displaces D1 from L2; D1 blocks allocate normally.
// After this kernel, L2 (126MB) holds ~all of D1 (128MB) for the gather.
// Voter arithmetic per column BIT-IDENTICAL to passing R7-R13:
//   seq  : strict sequential chain over k
//   IC4  : a[k%4] accumulators in increasing k, left-chain combine
//   truth: exact fixed-point int64 (order-free)
// 256 threads/block, grid (B, 2).
// ---------------------------------------------------------------------------
__global__ __launch_bounds__(256) void colsum_kernel(const float* __restrict__ D1,
                                                     const float* __restrict__ D2) {
    const int b     = blockIdx.x;
    const int which = blockIdx.y;
    const int tid   = threadIdx.x;

    const float4* q = (const float4*)((which ? D2 : D1) + (size_t)b * NN * NN);
    float*     oss = (which ? g_ss2 : g_ss1) + b * NN;
    float*     ov4 = (which ? g_v42 : g_v41) + b * NN;
    long long* ovi = (which ? g_vi2 : g_vi1) + b * NN;

    uint64_t pol;
    asm("createpolicy.fractional.L2::evict_first.b64 %0, 1.0;" : "=l"(pol));

    __shared__ float tile[2][TK * NN];   // 2 x 16KB

    // One 16KB tile: 1024 float4 slots, 4 per thread, coalesced.
    // D2 (which=1): evict_first hint. D1 (which=0): normal allocation.
    #define LOAD_TILE(buf, t0)                                                 \
        {                                                                      \
            uint32_t _base = (uint32_t)__cvta_generic_to_shared(&tile[buf][0]);\
            if (which) {                                                       \
                _Pragma("unroll")                                              \
                for (int m = 0; m < 4; ++m) {                                  \
                    int idx = m * 256 + tid;                                   \
                    asm volatile(                                              \
                        "cp.async.cg.shared.global.L2::cache_hint "            \
                        "[%0], [%1], 16, %2;\n"                                \
                        :: "r"(_base + idx * 16),                              \
                           "l"(q + (size_t)(t0) * 64 + idx), "l"(pol)          \
                        : "memory");                                           \
                }                                                              \
            } else {                                                           \
                _Pragma("unroll")                                              \
                for (int m = 0; m < 4; ++m) {                                  \
                    int idx = m * 256 + tid;                                   \
                    asm volatile("cp.async.cg.shared.global [%0], [%1], 16;\n" \
                                 :: "r"(_base + idx * 16),                     \
                                    "l"(q + (size_t)(t0) * 64 + idx)           \
                                 : "memory");                                  \
                }                                                              \
            }                                                                  \
            asm volatile("cp.async.commit_group;\n" ::: "memory");             \
        }

    float ss = 0.f, a0 = 0.f, a1 = 0.f, a2 = 0.f, a3 = 0.f;
    long long acc = 0;
    const float SCALE = 1099511627776.0f;   // 2^40 (exact power-of-two scale)

    LOAD_TILE(0, 0);

#pragma unroll 1
    for (int ti = 0; ti < NT; ++ti) {
        if (ti + 1 < NT) {
            LOAD_TILE((ti + 1) & 1, (ti + 1) * TK);
            asm volatile("cp.async.wait_group 1;\n" ::: "memory");
        } else {
            asm volatile("cp.async.wait_group 0;\n" ::: "memory");
        }
        __syncthreads();

        const float* T = &tile[ti & 1][0];
        float x[TK];
#pragma unroll
        for (int r = 0; r < TK; ++r) x[r] = T[r * NN + tid];   // conflict-free

        // strict sequential chain (identical order to R7-R13)
#pragma unroll
        for (int r = 0; r < TK; ++r) ss = __fadd_rn(ss, x[r]);
        // IC4 round-robin: k = ti*16 + r, k%4 == r%4 (TK multiple of 4)
#pragma unroll
        for (int r = 0; r < TK; r += 4) {
            a0 = __fadd_rn(a0, x[r + 0]);
            a1 = __fadd_rn(a1, x[r + 1]);
            a2 = __fadd_rn(a2, x[r + 2]);
            a3 = __fadd_rn(a3, x[r + 3]);
        }
        // exact fixed-point truth (order-free)
#pragma unroll
        for (int r = 0; r < TK; ++r) acc += __float2ll_rn(x[r] * SCALE);

        __syncthreads();
    }
    #undef LOAD_TILE

    oss[tid] = ss;
    ov4[tid] = __fadd_rn(__fadd_rn(__fadd_rn(a0, a1), a2), a3);
    ovi[tid] = acc;
}

// ---------------------------------------------------------------------------
// Sort: bitonic lexsort per batch with majority comparator over the three
// voter orders (type primary; per-voter index tie-break). Also writes the
// gathered-types output tail.
// ---------------------------------------------------------------------------
__global__ void sort_kernel(const int* __restrict__ t1,
                            const int* __restrict__ t2,
                            float* __restrict__ out,
                            long long base, long long out_size) {
    const int b   = blockIdx.x;
    const int tid = threadIdx.x;

    __shared__ float     vs1[NN], v41[NN];
    __shared__ long long vi1[NN];
    __shared__ float     vs2[NN], v42[NN];
    __shared__ long long vi2[NN];
    __shared__ int       ty1s[NN], ty2s[NN];
    __shared__ int       idx1[NN], idx2[NN];

    vs1[tid] = g_ss1[b * NN + tid];
    v41[tid] = g_v41[b * NN + tid];
    vi1[tid] = g_vi1[b * NN + tid];
    vs2[tid] = g_ss2[b * NN + tid];
    v42[tid] = g_v42[b * NN + tid];
    vi2[tid] = g_vi2[b * NN + tid];
    ty1s[tid] = t1[b * NN + tid];
    ty2s[tid] = t2[b * NN + tid];
    idx1[tid] = tid;
    idx2[tid] = tid;
    __syncthreads();

    #define BEFORE(ty, vsq, v4a, vib, i, j, res)                              \
        {                                                                     \
            int _ti = ty[i], _tj = ty[j];                                     \
            if (_ti != _tj) { res = (_ti < _tj); }                            \
            else {                                                            \
                int _v = 0;                                                   \
                _v += (vsq[i] < vsq[j]) || (vsq[i] == vsq[j] && (i) < (j));   \
                _v += (v4a[i] < v4a[j]) || (v4a[i] == v4a[j] && (i) < (j));   \
                _v += (vib[i] < vib[j]) || (vib[i] == vib[j] && (i) < (j));   \
                res = (_v >= 2);                                              \
            }                                                                 \
        }

    for (int k = 2; k <= NN; k <<= 1) {
        for (int j = k >> 1; j > 0; j >>= 1) {
            int partner = tid ^ j;
            if (partner > tid) {
                bool up = ((tid & k) == 0);
                {
                    int ia = idx1[tid], ib = idx1[partner];
                    bool a_before_b;
                    BEFORE(ty1s, vs1, v41, vi1, ia, ib, a_before_b);
                    if (up == !a_before_b) { idx1[tid] = ib; idx1[partner] = ia; }
                }
                {
                    int ia = idx2[tid], ib = idx2[partner];
                    bool a_before_b;
                    BEFORE(ty2s, vs2, v42, vi2, ia, ib, a_before_b);
                    if (up == !a_before_b) { idx2[tid] = ib; idx2[partner] = ia; }
                }
            }
            __syncthreads();
        }
    }
    #undef BEFORE

    // perm[order2[t]] = order1[t]
    g_perm[b * NN + idx2[tid]] = idx1[tid];

    // gathered-types tail: out[base + b*NN + pos] = types1[source atom]
    long long o = base + (long long)b * NN + idx2[tid];
    if (o < out_size) out[o] = (float)ty1s[idx1[tid]];
}

// ---------------------------------------------------------------------------
// Gather: out[b,i,j] = D1[b, perm[i], perm[j]]. GR rows per block; float4
// loads (should hit L2 — D1 retained by the eviction policies) and float4
// STREAMING stores (__stcs, evict-first: output never re-read, so it must
// not displace D1 from L2 mid-kernel).
// ---------------------------------------------------------------------------
__global__ void gather_kernel(const float* __restrict__ D1,
                              float* __restrict__ out) {
    const int b   = blockIdx.y;
    const int i0  = blockIdx.x * GR;
    const int tid = threadIdx.x;   // 256 threads

    __shared__ int   sp[NN];
    __shared__ float sd[GR][NN];

    sp[tid] = g_perm[b * NN + tid];
    __syncthreads();

    const float4* src4 = (const float4*)(D1 + (size_t)b * NN * NN);
#pragma unroll
    for (int m = 0; m < GR * 64 / 256; ++m) {
        int q  = m * 256 + tid;     // over GR*64 float4 slots
        int r  = q >> 6;            // row
        int c4 = q & 63;
        int s  = sp[i0 + r];
        ((float4*)sd[r])[c4] = src4[(size_t)s * 64 + c4];
    }
    __syncthreads();

    float4* ob = (float4*)(out + ((size_t)b * NN + i0) * NN);
#pragma unroll
    for (int m = 0; m < GR * 64 / 256; ++m) {
        int q  = m * 256 + tid;
        int r  = q >> 6;
        int c4 = q & 63;
        float4 v;
        v.x = sd[r][sp[c4 * 4 + 0]];
        v.y = sd[r][sp[c4 * 4 + 1]];
        v.z = sd[r][sp[c4 * 4 + 2]];
        v.w = sd[r][sp[c4 * 4 + 3]];
        __stcs(&ob[(size_t)r * 64 + c4], v);   // streaming store, evict-first
    }
}

extern "C" void kernel_launch(void* const* d_in, const int* in_sizes, int n_in,
                              void* d_out, int out_size) {
    const float* D1 = (const float*)d_in[0];
    const float* D2 = (const float*)d_in[1];
    const int*   t1 = (const int*)d_in[2];
    const int*   t2 = (const int*)d_in[3];
    float* out = (float*)d_out;

    int B = in_sizes[0] / (NN * NN);
    if (B > MAXB) B = MAXB;

    dim3 cgr(B, 2);
    colsum_kernel<<<cgr, 256>>>(D1, D2);

    long long base = (long long)B * NN * NN;
    sort_kernel<<<B, NN>>>(t1, t2, out, base, (long long)out_size);

    dim3 ggrid(NN / GR, B);
    gather_kernel<<<ggrid, 256>>>(D1, out);
}

// round 17
// speedup vs baseline: 1.1619x; 1.0571x over previous
#include <cuda_runtime.h>
#include <cuda_bf16.h>
#include <stdint.h>

#define NN 256            // N (atoms per batch)
#define MAXB 512          // max batch
#define GR 16             // output rows per gather block
#define TK 16             // tile rows for colsum staging
#define NT (NN / TK)      // 16 tiles

__device__ int       g_perm[MAXB * NN];
__device__ int       g_flag[MAXB];          // zero-initialized; reset each use
__device__ float     g_ss1[MAXB * NN], g_v41[MAXB * NN];
__device__ long long g_vi1[MAXB * NN];
__device__ float     g_ss2[MAXB * NN], g_v42[MAXB * NN];
__device__ long long g_vi2[MAXB * NN];

// ---------------------------------------------------------------------------
// colsum + fused sort. Grid (B, 2): block (b,0) sums D1[b], (b,1) sums D2[b]
// (D2 with L2 evict_first so it never displaces D1). Each block publishes its
// sums, fences, and bumps g_flag[b]; the SECOND finisher runs the bitonic
// majority-vote lexsort for batch b in its now-free tile smem, writes perm +
// the gathered-types tail, and resets the flag (single writer; next graph
// replay sees 0). No block ever waits -> no deadlock possible.
// Voter arithmetic per column BIT-IDENTICAL to passing R7-R16:
//   seq  : strict sequential chain over k
//   IC4  : a[k%4] accumulators in increasing k, left-chain combine
//   truth: exact fixed-point int64 (order-free)
// ---------------------------------------------------------------------------
__global__ __launch_bounds__(256) void colsum_sort_kernel(
    const float* __restrict__ D1, const float* __restrict__ D2,
    const int* __restrict__ t1, const int* __restrict__ t2,
    float* __restrict__ out, long long base, long long out_size)
{
    const int b     = blockIdx.x;
    const int which = blockIdx.y;
    const int tid   = threadIdx.x;

    const float4* q = (const float4*)((which ? D2 : D1) + (size_t)b * NN * NN);
    float*     oss = (which ? g_ss2 : g_ss1) + b * NN;
    float*     ov4 = (which ? g_v42 : g_v41) + b * NN;
    long long* ovi = (which ? g_vi2 : g_vi1) + b * NN;

    uint64_t pol;
    asm("createpolicy.fractional.L2::evict_first.b64 %0, 1.0;" : "=l"(pol));

    __shared__ float tile[2][TK * NN];   // 32 KB ring; reused by the sort

    #define LOAD_TILE(buf, t0)                                                 \
        {                                                                      \
            uint32_t _base = (uint32_t)__cvta_generic_to_shared(&tile[buf][0]);\
            if (which) {                                                       \
                _Pragma("unroll")                                              \
                for (int m = 0; m < 4; ++m) {                                  \
                    int idx = m * 256 + tid;                                   \
                    asm volatile(                                              \
                        "cp.async.cg.shared.global.L2::cache_hint "            \
                        "[%0], [%1], 16, %2;\n"                                \
                        :: "r"(_base + idx * 16),                              \
                           "l"(q + (size_t)(t0) * 64 + idx), "l"(pol)          \
                        : "memory");                                           \
                }                                                              \
            } else {                                                           \
                _Pragma("unroll")                                              \
                for (int m = 0; m < 4; ++m) {                                  \
                    int idx = m * 256 + tid;                                   \
                    asm volatile("cp.async.cg.shared.global [%0], [%1], 16;\n" \
                                 :: "r"(_base + idx * 16),                     \
                                    "l"(q + (size_t)(t0) * 64 + idx)           \
                                 : "memory");                                  \
                }                                                              \
            }                                                                  \
            asm volatile("cp.async.commit_group;\n" ::: "memory");             \
        }

    float ss = 0.f, a0 = 0.f, a1 = 0.f, a2 = 0.f, a3 = 0.f;
    long long acc = 0;
    const float SCALE = 1099511627776.0f;   // 2^40 (exact power-of-two scale)

    LOAD_TILE(0, 0);

#pragma unroll 1
    for (int ti = 0; ti < NT; ++ti) {
        if (ti + 1 < NT) {
            LOAD_TILE((ti + 1) & 1, (ti + 1) * TK);
            asm volatile("cp.async.wait_group 1;\n" ::: "memory");
        } else {
            asm volatile("cp.async.wait_group 0;\n" ::: "memory");
        }
        __syncthreads();

        const float* T = &tile[ti & 1][0];
        float x[TK];
#pragma unroll
        for (int r = 0; r < TK; ++r) x[r] = T[r * NN + tid];   // conflict-free

        // strict sequential chain (identical order to R7-R16)
#pragma unroll
        for (int r = 0; r < TK; ++r) ss = __fadd_rn(ss, x[r]);
        // IC4 round-robin: k = ti*16 + r, k%4 == r%4 (TK multiple of 4)
#pragma unroll
        for (int r = 0; r < TK; r += 4) {
            a0 = __fadd_rn(a0, x[r + 0]);
            a1 = __fadd_rn(a1, x[r + 1]);
            a2 = __fadd_rn(a2, x[r + 2]);
            a3 = __fadd_rn(a3, x[r + 3]);
        }
        // exact fixed-point truth (order-free)
#pragma unroll
        for (int r = 0; r < TK; ++r) acc += __float2ll_rn(x[r] * SCALE);

        __syncthreads();
    }
    #undef LOAD_TILE

    oss[tid] = ss;
    ov4[tid] = __fadd_rn(__fadd_rn(__fadd_rn(a0, a1), a2), a3);
    ovi[tid] = acc;

    // ---- handshake: second finisher of batch b runs the sort ----
    __threadfence();                       // release our sums
    __syncthreads();
    __shared__ int who;
    if (tid == 0) who = atomicAdd(&g_flag[b], 1);
    __syncthreads();
    if (who == 0) return;                  // first finisher exits
    __threadfence();                       // acquire partner's sums

    // Sort arrays carved out of the (now free) tile smem: 12 KB < 32 KB.
    char* sm = (char*)&tile[0][0];
    float*     vs1  = (float*)sm;                         // 1 KB
    float*     v41  = vs1 + NN;                           // 1 KB
    float*     vs2  = v41 + NN;                           // 1 KB
    float*     v42  = vs2 + NN;                           // 1 KB
    long long* vi1  = (long long*)(v42 + NN);             // 2 KB
    long long* vi2  = vi1 + NN;                           // 2 KB
    int*       ty1s = (int*)(vi2 + NN);                   // 1 KB
    int*       ty2s = ty1s + NN;
    int*       idx1 = ty2s + NN;
    int*       idx2 = idx1 + NN;

    vs1[tid] = g_ss1[b * NN + tid];
    v41[tid] = g_v41[b * NN + tid];
    vi1[tid] = g_vi1[b * NN + tid];
    vs2[tid] = g_ss2[b * NN + tid];
    v42[tid] = g_v42[b * NN + tid];
    vi2[tid] = g_vi2[b * NN + tid];
    ty1s[tid] = t1[b * NN + tid];
    ty2s[tid] = t2[b * NN + tid];
    idx1[tid] = tid;
    idx2[tid] = tid;
    __syncthreads();

    #define BEFORE(ty, vsq, v4a, vib, i, j, res)                              \
        {                                                                     \
            int _ti = ty[i], _tj = ty[j];                                     \
            if (_ti != _tj) { res = (_ti < _tj); }                            \
            else {                                                            \
                int _v = 0;                                                   \
                _v += (vsq[i] < vsq[j]) || (vsq[i] == vsq[j] && (i) < (j));   \
                _v += (v4a[i] < v4a[j]) || (v4a[i] == v4a[j] && (i) < (j));   \
                _v += (vib[i] < vib[j]) || (vib[i] == vib[j] && (i) < (j));   \
                res = (_v >= 2);                                              \
            }                                                                 \
        }

    for (int k = 2; k <= NN; k <<= 1) {
        for (int j = k >> 1; j > 0; j >>= 1) {
            int partner = tid ^ j;
            if (partner > tid) {
                bool up = ((tid & k) == 0);
                {
                    int ia = idx1[tid], ib = idx1[partner];
                    bool a_before_b;
                    BEFORE(ty1s, vs1, v41, vi1, ia, ib, a_before_b);
                    if (up == !a_before_b) { idx1[tid] = ib; idx1[partner] = ia; }
                }
                {
                    int ia = idx2[tid], ib = idx2[partner];
                    bool a_before_b;
                    BEFORE(ty2s, vs2, v42, vi2, ia, ib, a_before_b);
                    if (up == !a_before_b) { idx2[tid] = ib; idx2[partner] = ia; }
                }
            }
            __syncthreads();
        }
    }
    #undef BEFORE

    // perm[order2[t]] = order1[t]
    g_perm[b * NN + idx2[tid]] = idx1[tid];

    // gathered-types tail: out[base + b*NN + pos] = types1[source atom]
    long long o = base + (long long)b * NN + idx2[tid];
    if (o < out_size) out[o] = (float)ty1s[idx1[tid]];

    if (tid == 0) g_flag[b] = 0;   // reset for next graph replay
}

// ---------------------------------------------------------------------------
// Gather: out[b,i,j] = D1[b, perm[i], perm[j]]. GR rows per block; float4
// loads (mostly L2 hits) and float4 streaming stores.
// ---------------------------------------------------------------------------
__global__ void gather_kernel(const float* __restrict__ D1,
                              float* __restrict__ out) {
    const int b   = blockIdx.y;
    const int i0  = blockIdx.x * GR;
    const int tid = threadIdx.x;   // 256 threads

    __shared__ int   sp[NN];
    __shared__ float sd[GR][NN];

    sp[tid] = g_perm[b * NN + tid];
    __syncthreads();

    const float4* src4 = (const float4*)(D1 + (size_t)b * NN * NN);
#pragma unroll
    for (int m = 0; m < GR * 64 / 256; ++m) {
        int q  = m * 256 + tid;     // over GR*64 float4 slots
        int r  = q >> 6;            // row
        int c4 = q & 63;
        int s  = sp[i0 + r];
        ((float4*)sd[r])[c4] = src4[(size_t)s * 64 + c4];
    }
    __syncthreads();

    float4* ob = (float4*)(out + ((size_t)b * NN + i0) * NN);
#pragma unroll
    for (int m = 0; m < GR * 64 / 256; ++m) {
        int q  = m * 256 + tid;
        int r  = q >> 6;
        int c4 = q & 63;
        float4 v;
        v.x = sd[r][sp[c4 * 4 + 0]];
        v.y = sd[r][sp[c4 * 4 + 1]];
        v.z = sd[r][sp[c4 * 4 + 2]];
        v.w = sd[r][sp[c4 * 4 + 3]];
        __stcs(&ob[(size_t)r * 64 + c4], v);   // streaming store, evict-first
    }
}

extern "C" void kernel_launch(void* const* d_in, const int* in_sizes, int n_in,
                              void* d_out, int out_size) {
    const float* D1 = (const float*)d_in[0];
    const float* D2 = (const float*)d_in[1];
    const int*   t1 = (const int*)d_in[2];
    const int*   t2 = (const int*)d_in[3];
    float* out = (float*)d_out;

    int B = in_sizes[0] / (NN * NN);
    if (B > MAXB) B = MAXB;

    long long base = (long long)B * NN * NN;

    dim3 cgr(B, 2);
    colsum_sort_kernel<<<cgr, 256>>>(D1, D2, t1, t2, out, base,
                                     (long long)out_size);

    dim3 ggrid(NN / GR, B);
    gather_kernel<<<ggrid, 256>>>(D1, out);
}